// round 13
// baseline (speedup 1.0000x reference)
#include <cuda_runtime.h>
#include <cooperative_groups.h>
#include <math.h>

namespace cg = cooperative_groups;

#define BB 128
#define HH 64
#define WW 64
#define AA 9
#define NN (HH*WW*AA)           // 36864 predictions per image
#define HALF (NN/2)             // per-rank stream share
#define KK 100
#define NBUCK 2048
#define CAP 1024                // candidate capacity per image
#define THREADS 1024
#define DS_ 1024.0f
#define STRIDE_ 64.0f
#define EPS_ 1e-7f
#define T0_ 1.25f               // static logit collect-threshold (fallback-guarded)

// globals (zero-initialized at load; kernel self-resets for graph replay)
__device__ float g_scratch[BB * 4];
__device__ unsigned g_done;

__device__ __forceinline__ unsigned fkey(float x) {
    unsigned u = __float_as_uint(x);
    return (u & 0x80000000u) ? ~u : (u | 0x80000000u);
}

__device__ __forceinline__ unsigned long long make_cand(float x, int e) {
    float conf = 1.0f / (1.0f + __expf(-x));           // conf in (0,1)
    unsigned ck = __float_as_uint(conf) ^ 0x80000000u; // order-preserving (conf>0)
    return ((unsigned long long)ck << 32) | (unsigned)(0xFFFFFFFFu - (unsigned)e);
}

// build clipped+fixed box corners for record e of image slice ip
__device__ __forceinline__ float4 build_box(const float* __restrict__ ip,
                                            const float* __restrict__ anc, int e) {
    const float* rec = ip + (size_t)e * 5;
    float o0 = __ldg(rec + 0), o1 = __ldg(rec + 1);
    float o2 = __ldg(rec + 2), o3 = __ldg(rec + 3);
    int a = e % AA;
    int w = (e / AA) % WW;
    int h = e / (AA * WW);
    float px = (1.0f / (1.0f + __expf(-o0)) + (float)w) * STRIDE_;
    float py = (1.0f / (1.0f + __expf(-o1)) + (float)h) * STRIDE_;
    float pw = __expf(o2) * __ldg(anc + 2 * a + 0) * DS_;
    float ph = __expf(o3) * __ldg(anc + 2 * a + 1) * DS_;
    float c0 = px - pw * 0.5f, c1 = py - ph * 0.5f;
    float c2 = px + pw * 0.5f, c3 = py + ph * 0.5f;
    c0 = fminf(fmaxf(c0, 0.0f), DS_); c1 = fminf(fmaxf(c1, 0.0f), DS_);
    c2 = fminf(fmaxf(c2, 0.0f), DS_); c3 = fminf(fmaxf(c3, 0.0f), DS_);
    float x1 = fminf(c0, c2), x2 = fmaxf(c0, c2);
    float y1 = fminf(c1, c3), y2 = fmaxf(c1, c3);
    if (x1 == x2) x2 = x1 + 1.0f;
    if (y1 == y2) y2 = y1 + 1.0f;
    return make_float4(x1, y1, x2, y2);
}

__global__ __launch_bounds__(THREADS, 2) __cluster_dims__(2, 1, 1)
void fused_kernel(const float* __restrict__ out5,
                  const float* __restrict__ tboxes,
                  const float* __restrict__ anchors,
                  float* __restrict__ out)
{
    __shared__ unsigned long long s_key[CAP];          // 8KB (rank0 authoritative)
    __shared__ float4 s_box[CAP];                      // 16KB
    __shared__ unsigned s_hist[NBUCK];                 // 8KB (fallback only)
    __shared__ unsigned s_fpart[THREADS / 32];
    __shared__ int s_sele[KK];
    __shared__ float s_selc[KK];
    __shared__ float s_bx1[KK], s_by1[KK], s_bx2[KK], s_by2[KK], s_ba[KK];
    __shared__ float s_tx1[KK], s_ty1[KK], s_tx2[KK], s_ty2[KK];
    __shared__ unsigned long long s_best[KK];
    __shared__ unsigned s_sup[KK][4];
    __shared__ unsigned s_kw[4];
    __shared__ int s_cnt, s_bsel, s_last;
    __shared__ float s_red[3][THREADS / 32];
    __shared__ unsigned s_cpart[THREADS / 32];

    cg::cluster_group cluster = cg::this_cluster();
    const unsigned rank = cluster.block_rank();
    const int tid = threadIdx.x;
    const int img = blockIdx.x >> 1;
    const float* __restrict__ ip = out5 + (size_t)img * NN * 5;

    // remote views of rank0's candidate buffer (rank0 maps to itself)
    int* r_cnt = cluster.map_shared_rank(&s_cnt, 0);
    unsigned long long* r_key = cluster.map_shared_rank(s_key, 0);
    float4* r_box = cluster.map_shared_rank(s_box, 0);

    if (rank == 0) {
        if (tid == 0) { s_cnt = 0; s_kw[0] = s_kw[1] = s_kw[2] = s_kw[3] = 0; }
        if (tid < KK * 4) ((unsigned*)s_sup)[tid] = 0;
        // targets early: DRAM latency overlaps the stream
        if (tid < KK) {
            const float* tp = tboxes + ((size_t)img * KK + tid) * 4;
            float t0 = fminf(fmaxf(__ldg(tp + 0), 0.0f), DS_);
            float t1 = fminf(fmaxf(__ldg(tp + 1), 0.0f), DS_);
            float t2 = fminf(fmaxf(__ldg(tp + 2), 0.0f), DS_);
            float t3 = fminf(fmaxf(__ldg(tp + 3), 0.0f), DS_);
            float tx1 = fminf(t0, t2), tx2 = fmaxf(t0, t2);
            float ty1 = fminf(t1, t3), ty2 = fmaxf(t1, t3);
            if (tx1 == tx2) tx2 = tx1 + 1.0f;
            if (ty1 == ty2) ty2 = ty1 + 1.0f;
            s_tx1[tid] = tx1; s_ty1[tid] = ty1; s_tx2[tid] = tx2; s_ty2[tid] = ty2;
        }
    }
    cluster.sync();     // s_cnt init visible to both ranks before streaming

    // ========== phase 1: both ranks stream half, push to rank0 smem ==========
    {
        const int base = (int)rank * HALF;
        #pragma unroll 6
        for (int i = tid; i < HALF; i += THREADS) {
            int e = base + i;
            float x = __ldg(&ip[(size_t)e * 5 + 4]);
            if (x > T0_) {
                int q = atomicAdd(r_cnt, 1);
                if (q < CAP) {
                    r_key[q] = make_cand(x, e);
                    r_box[q] = build_box(ip, anchors, e);
                }
            }
        }
    }
    cluster.sync();     // release(writes) / acquire before rank0 reads

    if (rank != 0) return;   // rank1 done; rank0 runs the tail on local smem

    const int scnt = s_cnt;
    const bool fb = (scnt < KK || scnt > CAP);

    // ---- fallback: exact histogram top-K over full image (never taken) ----
    if (fb) {
        for (int i = tid; i < NBUCK; i += THREADS) s_hist[i] = 0;
        if (tid == 0) s_cnt = 0;
        __syncthreads();
        for (int e = tid; e < NN; e += THREADS) {
            float x = ip[(size_t)e * 5 + 4];
            atomicAdd(&s_hist[fkey(x) >> 21], 1u);
        }
        __syncthreads();
        if (tid < 32) {
            unsigned s = 0;
            int base = tid * (NBUCK / 32);
            #pragma unroll
            for (int j = 0; j < NBUCK / 32; j++) s += s_hist[base + j];
            s_fpart[tid] = s;
        }
        __syncthreads();
        if (tid == 0) {
            unsigned cum = 0; int sg = 0;
            for (int t = 31; t >= 0; t--) {
                if (cum + s_fpart[t] >= KK) { sg = t; break; }
                cum += s_fpart[t];
            }
            int bsel = sg * (NBUCK / 32);
            for (int b = sg * (NBUCK / 32) + (NBUCK / 32) - 1;
                 b >= sg * (NBUCK / 32); b--) {
                cum += s_hist[b];
                if (cum >= KK) { bsel = b; break; }
            }
            s_bsel = bsel;
        }
        __syncthreads();
        const int bsel = s_bsel;
        for (int e = tid; e < NN; e += THREADS) {
            float x = ip[(size_t)e * 5 + 4];
            if ((int)(fkey(x) >> 21) >= bsel) {
                int pos = atomicAdd(&s_cnt, 1);
                if (pos < CAP) {
                    s_key[pos] = make_cand(x, e);
                    s_box[pos] = build_box(ip, anchors, e);
                }
            }
        }
        __syncthreads();
    }

    const int C = min(s_cnt, CAP);

    // ---- rank selection: exact top-K (keys unique) ----
    for (int c = tid; c < C; c += THREADS) {
        unsigned long long key = s_key[c];
        int rnk = 0;
        #pragma unroll 8
        for (int j = 0; j < C; j++) rnk += (s_key[j] > key) ? 1 : 0;
        if (rnk < KK) {
            s_sele[rnk] = c;
            s_selc[rnk] = __uint_as_float((unsigned)(key >> 32) ^ 0x80000000u);
        }
    }
    __syncthreads();

    if (tid < KK) {
        float4 b = s_box[s_sele[tid]];
        s_bx1[tid] = b.x; s_by1[tid] = b.y; s_bx2[tid] = b.z; s_by2[tid] = b.w;
        s_ba[tid] = (b.z - b.x) * (b.w - b.y);
        if (s_selc[tid] >= 0.5f) atomicOr(&s_kw[tid >> 5], 1u << (tid & 31));
    }
    __syncthreads();

    // ---- pairwise pred-pred suppression bitmask (conditional atomics, rare) ----
    for (int q = tid; q < KK * KK; q += THREADS) {
        int i = q % KK, j = q / KK;
        if (j > i) {
            float lx = fmaxf(s_bx1[i], s_bx1[j]);
            float ly = fmaxf(s_by1[i], s_by1[j]);
            float rx = fminf(s_bx2[i], s_bx2[j]);
            float ry = fminf(s_by2[i], s_by2[j]);
            float iw = fmaxf(rx - lx, 0.0f), ih = fmaxf(ry - ly, 0.0f);
            float inter = iw * ih;
            float iou = __fdividef(inter, s_ba[i] + s_ba[j] - inter + EPS_);
            if (iou > 0.5f) atomicOr(&s_sup[i][j >> 5], 1u << (j & 31));
        }
    }
    __syncthreads();

    // ---- greedy NMS sweep (exact reference semantics), serial in thread 0 ----
    if (tid == 0) {
        const uint4* supv = (const uint4*)s_sup;
        unsigned kw0 = s_kw[0], kw1 = s_kw[1], kw2 = s_kw[2], kw3 = s_kw[3];
        #pragma unroll 4
        for (int i = 0; i < KK; i++) {
            uint4 r = supv[i];
            unsigned wv = (i < 32) ? kw0 : (i < 64) ? kw1 : (i < 96) ? kw2 : kw3;
            if ((wv >> (i & 31)) & 1u) {
                kw0 &= ~r.x; kw1 &= ~r.y; kw2 &= ~r.z; kw3 &= ~r.w;
            }
        }
        s_kw[0] = kw0; s_kw[1] = kw1; s_kw[2] = kw2; s_kw[3] = kw3;
    }
    __syncthreads();

    // ---- per-target max-IoU argmax: warp-owned targets, shuffle reduce ----
    {
        const int w = tid >> 5, l = tid & 31;
        unsigned kw[4] = { s_kw[0], s_kw[1], s_kw[2], s_kw[3] };
        for (int t = w; t < KK; t += THREADS / 32) {
            float tx1 = s_tx1[t], ty1 = s_ty1[t], tx2 = s_tx2[t], ty2 = s_ty2[t];
            float ta = (tx2 - tx1) * (ty2 - ty1);
            unsigned long long best = 0ull;
            #pragma unroll
            for (int p = l; p < KK + 28; p += 32) {
                if (p < KK) {
                    float kf = ((kw[p >> 5] >> (p & 31)) & 1u) ? 1.0f : 0.0f;
                    float lx = fmaxf(s_bx1[p], tx1);
                    float ly = fmaxf(s_by1[p], ty1);
                    float rx = fminf(s_bx2[p], tx2);
                    float ry = fminf(s_by2[p], ty2);
                    float iw = fmaxf(rx - lx, 0.0f), ih = fmaxf(ry - ly, 0.0f);
                    float inter = iw * ih;
                    float iou = __fdividef(inter, s_ba[p] + ta - inter + EPS_);
                    float v = iou * kf;
                    unsigned long long key =
                        ((unsigned long long)__float_as_uint(v) << 32)
                        | (unsigned)(0xFFFFFFFFu - (unsigned)p);
                    best = (key > best) ? key : best;
                }
            }
            #pragma unroll
            for (int off = 16; off; off >>= 1) {
                unsigned long long o = __shfl_down_sync(0xFFFFFFFFu, best, off);
                best = (o > best) ? o : best;
            }
            if (l == 0) s_best[t] = best;
        }
    }
    __syncthreads();

    // ---- per-target DIoU + penalty terms ----
    float diou = 0.0f, lowv = 0.0f, highv = 0.0f;
    if (tid < KK) {
        unsigned long long key = s_best[tid];
        float max_iou = fmaxf(__uint_as_float((unsigned)(key >> 32)), 0.0f);
        int best = (int)(0xFFFFFFFFu - (unsigned)(key & 0xFFFFFFFFull));
        float tx1 = s_tx1[tid], ty1 = s_ty1[tid], tx2 = s_tx2[tid], ty2 = s_ty2[tid];
        float pbx1 = s_bx1[best], pby1 = s_by1[best];
        float pbx2 = s_bx2[best], pby2 = s_by2[best];
        float pcx = (pbx1 + pbx2) * 0.5f, pcy = (pby1 + pby2) * 0.5f;
        float tcx = (tx1 + tx2) * 0.5f,  tcy = (ty1 + ty2) * 0.5f;
        float cd = (pcx - tcx) * (pcx - tcx) + (pcy - tcy) * (pcy - tcy);
        float ex1 = fminf(pbx1, tx1), ey1 = fminf(pby1, ty1);
        float ex2 = fmaxf(pbx2, tx2), ey2 = fmaxf(pby2, ty2);
        float dg = (ex2 - ex1) * (ex2 - ex1) + (ey2 - ey1) * (ey2 - ey1);
        diou = 1.0f - (max_iou - __fdividef(cd, dg + EPS_));

        float kfr = ((s_kw[tid >> 5] >> (tid & 31)) & 1u) ? 1.0f : 0.0f;
        float val = s_selc[tid];
        lowv  = fmaxf(-val, 0.0f) * kfr;
        highv = fmaxf(val - 1.0f, 0.0f) * kfr;
    }

    // deterministic reduction
    #pragma unroll
    for (int off = 16; off; off >>= 1) {
        diou  += __shfl_down_sync(0xFFFFFFFFu, diou,  off);
        lowv  += __shfl_down_sync(0xFFFFFFFFu, lowv,  off);
        highv += __shfl_down_sync(0xFFFFFFFFu, highv, off);
    }
    if ((tid & 31) == 0) {
        s_red[0][tid >> 5] = diou;
        s_red[1][tid >> 5] = lowv;
        s_red[2][tid >> 5] = highv;
    }
    __syncthreads();
    if (tid == 0) {
        float d = 0.0f, l = 0.0f, h = 0.0f;
        #pragma unroll
        for (int w = 0; w < 4; w++) {           // only warps 0-3 hold tid<KK data
            d += s_red[0][w]; l += s_red[1][w]; h += s_red[2][w];
        }
        float cnt = (float)(__popc(s_kw[0]) + __popc(s_kw[1]) +
                            __popc(s_kw[2]) + __popc(s_kw[3]));
        g_scratch[img * 4 + 0] = d;
        g_scratch[img * 4 + 1] = l;
        g_scratch[img * 4 + 2] = h;
        g_scratch[img * 4 + 3] = cnt;
        __threadfence();
        unsigned t = atomicAdd(&g_done, 1u);
        s_last = (t == BB - 1) ? 1 : 0;
    }
    __syncthreads();

    // ---- last rank0 CTA performs the global finalize ----
    if (s_last) {
        __threadfence();
        float d = 0.0f, l = 0.0f, h = 0.0f, c = 0.0f;
        if (tid < BB) {
            d = g_scratch[tid * 4 + 0];
            l = g_scratch[tid * 4 + 1];
            h = g_scratch[tid * 4 + 2];
            c = g_scratch[tid * 4 + 3];
        }
        #pragma unroll
        for (int off = 16; off; off >>= 1) {
            d += __shfl_down_sync(0xFFFFFFFFu, d, off);
            l += __shfl_down_sync(0xFFFFFFFFu, l, off);
            h += __shfl_down_sync(0xFFFFFFFFu, h, off);
            c += __shfl_down_sync(0xFFFFFFFFu, c, off);
        }
        if ((tid & 31) == 0) {
            s_red[0][tid >> 5] = d;
            s_red[1][tid >> 5] = l;
            s_red[2][tid >> 5] = h;
            s_cpart[tid >> 5]  = __float_as_uint(c);
        }
        __syncthreads();
        if (tid == 0) {
            float D = 0.0f, L = 0.0f, H = 0.0f, Cn = 0.0f;
            #pragma unroll
            for (int w = 0; w < 4; w++) {       // only warps 0-3 hold tid<BB data
                D += s_red[0][w]; L += s_red[1][w]; H += s_red[2][w];
                Cn += __uint_as_float(s_cpart[w]);
            }
            float n = fmaxf(Cn, 1.0f);
            out[0] = D / (float)(BB * KK) + L / n + 0.5f * (H / n);
            g_done = 0;                 // reset for next graph replay
        }
    }
}

extern "C" void kernel_launch(void* const* d_in, const int* in_sizes, int n_in,
                              void* d_out, int out_size)
{
    const float* output  = (const float*)d_in[0];   // (128,64,64,9,5) fp32
    const float* tboxes  = (const float*)d_in[1];   // (128,100,4) fp32
    const float* anchors = (const float*)d_in[2];   // (9,2) fp32
    float* out = (float*)d_out;

    fused_kernel<<<BB * 2, THREADS>>>(output, tboxes, anchors, out);
}

// round 15
// speedup vs baseline: 1.2653x; 1.2653x over previous
#include <cuda_runtime.h>
#include <math.h>

#define BB 128
#define HH 64
#define WW 64
#define AA 9
#define NN (HH*WW*AA)           // 36864 predictions per image
#define KK 100
#define NBUCK 2048
#define CAP 1024                // candidate capacity per image
#define THREADS 1024
#define BATCH 6                 // NN = 6 * BATCH * THREADS exactly
#define DS_ 1024.0f
#define STRIDE_ 64.0f
#define EPS_ 1e-7f
#define T0_ 1.25f               // static logit collect-threshold (fallback-guarded)

// globals (zero-initialized at load; kernel self-resets for graph replay)
__device__ float g_scratch[BB * 4];
__device__ unsigned g_done;

__device__ __forceinline__ unsigned fkey(float x) {
    unsigned u = __float_as_uint(x);
    return (u & 0x80000000u) ? ~u : (u | 0x80000000u);
}

__device__ __forceinline__ unsigned long long make_cand(float x, int e) {
    float conf = 1.0f / (1.0f + __expf(-x));           // conf in (0,1)
    unsigned ck = __float_as_uint(conf) ^ 0x80000000u; // order-preserving (conf>0)
    return ((unsigned long long)ck << 32) | (unsigned)(0xFFFFFFFFu - (unsigned)e);
}

// build clipped+fixed box corners for record e of image slice ip
__device__ __forceinline__ float4 build_box(const float* __restrict__ ip,
                                            const float* __restrict__ anc, int e) {
    const float* rec = ip + (size_t)e * 5;
    float o0 = __ldg(rec + 0), o1 = __ldg(rec + 1);
    float o2 = __ldg(rec + 2), o3 = __ldg(rec + 3);
    int a = e % AA;
    int w = (e / AA) % WW;
    int h = e / (AA * WW);
    float px = (1.0f / (1.0f + __expf(-o0)) + (float)w) * STRIDE_;
    float py = (1.0f / (1.0f + __expf(-o1)) + (float)h) * STRIDE_;
    float pw = __expf(o2) * __ldg(anc + 2 * a + 0) * DS_;
    float ph = __expf(o3) * __ldg(anc + 2 * a + 1) * DS_;
    float c0 = px - pw * 0.5f, c1 = py - ph * 0.5f;
    float c2 = px + pw * 0.5f, c3 = py + ph * 0.5f;
    c0 = fminf(fmaxf(c0, 0.0f), DS_); c1 = fminf(fmaxf(c1, 0.0f), DS_);
    c2 = fminf(fmaxf(c2, 0.0f), DS_); c3 = fminf(fmaxf(c3, 0.0f), DS_);
    float x1 = fminf(c0, c2), x2 = fmaxf(c0, c2);
    float y1 = fminf(c1, c3), y2 = fmaxf(c1, c3);
    if (x1 == x2) x2 = x1 + 1.0f;
    if (y1 == y2) y2 = y1 + 1.0f;
    return make_float4(x1, y1, x2, y2);
}

__global__ __launch_bounds__(THREADS)
void fused_kernel(const float* __restrict__ out5,
                  const float* __restrict__ tboxes,
                  const float* __restrict__ anchors,
                  float* __restrict__ out)
{
    __shared__ unsigned long long s_key[CAP];          // 8KB
    __shared__ float4 s_box[CAP];                      // 16KB
    __shared__ unsigned s_hist[NBUCK];                 // 8KB (fallback only)
    __shared__ unsigned s_fpart[THREADS / 32];
    __shared__ int s_sele[KK];
    __shared__ float s_selc[KK];
    __shared__ float s_bx1[KK], s_by1[KK], s_bx2[KK], s_by2[KK], s_ba[KK];
    __shared__ float s_tx1[KK], s_ty1[KK], s_tx2[KK], s_ty2[KK];
    __shared__ unsigned long long s_best[KK];
    __shared__ unsigned s_sup[KK][4];
    __shared__ unsigned s_kw[4];
    __shared__ int s_cnt, s_bsel, s_last;
    __shared__ float s_red[3][THREADS / 32];
    __shared__ unsigned s_cpart[THREADS / 32];

    const int tid = threadIdx.x;
    const int img = blockIdx.x;
    const float* __restrict__ ip = out5 + (size_t)img * NN * 5;

    if (tid == 0) { s_cnt = 0; s_kw[0] = s_kw[1] = s_kw[2] = s_kw[3] = 0; }
    if (tid < KK * 4) ((unsigned*)s_sup)[tid] = 0;

    // targets early: DRAM latency overlaps the stream
    if (tid < KK) {
        const float* tp = tboxes + ((size_t)img * KK + tid) * 4;
        float t0 = fminf(fmaxf(__ldg(tp + 0), 0.0f), DS_);
        float t1 = fminf(fmaxf(__ldg(tp + 1), 0.0f), DS_);
        float t2 = fminf(fmaxf(__ldg(tp + 2), 0.0f), DS_);
        float t3 = fminf(fmaxf(__ldg(tp + 3), 0.0f), DS_);
        float tx1 = fminf(t0, t2), tx2 = fmaxf(t0, t2);
        float ty1 = fminf(t1, t3), ty2 = fmaxf(t1, t3);
        if (tx1 == tx2) tx2 = tx1 + 1.0f;
        if (ty1 == ty2) ty2 = ty1 + 1.0f;
        s_tx1[tid] = tx1; s_ty1[tid] = ty1; s_tx2[tid] = tx2; s_ty2[tid] = ty2;
    }
    __syncthreads();

    // ========== phase 1: stream — explicit load-batch (MLP=BATCH) ===========
    for (int it = 0; it < NN / (BATCH * THREADS); it++) {
        const int e0 = it * BATCH * THREADS + tid;
        float xv[BATCH];
        #pragma unroll
        for (int k = 0; k < BATCH; k++)                 // BATCH independent LDGs
            xv[k] = __ldg(&ip[(size_t)(e0 + k * THREADS) * 5 + 4]);
        #pragma unroll
        for (int k = 0; k < BATCH; k++) {               // then the rare branch
            if (xv[k] > T0_) {
                int e = e0 + k * THREADS;
                int q = atomicAdd(&s_cnt, 1);
                if (q < CAP) {
                    s_key[q] = make_cand(xv[k], e);
                    s_box[q] = build_box(ip, anchors, e);
                }
            }
        }
    }
    __syncthreads();

    const int scnt = s_cnt;
    const bool fb = (scnt < KK || scnt > CAP);

    // ---- fallback: exact histogram top-K (never taken for typical inputs) ----
    if (fb) {
        for (int i = tid; i < NBUCK; i += THREADS) s_hist[i] = 0;
        if (tid == 0) s_cnt = 0;
        __syncthreads();
        for (int e = tid; e < NN; e += THREADS) {
            float x = ip[(size_t)e * 5 + 4];
            atomicAdd(&s_hist[fkey(x) >> 21], 1u);
        }
        __syncthreads();
        if (tid < 32) {
            unsigned s = 0;
            int base = tid * (NBUCK / 32);
            #pragma unroll
            for (int j = 0; j < NBUCK / 32; j++) s += s_hist[base + j];
            s_fpart[tid] = s;
        }
        __syncthreads();
        if (tid == 0) {
            unsigned cum = 0; int sg = 0;
            for (int t = 31; t >= 0; t--) {
                if (cum + s_fpart[t] >= KK) { sg = t; break; }
                cum += s_fpart[t];
            }
            int bsel = sg * (NBUCK / 32);
            for (int b = sg * (NBUCK / 32) + (NBUCK / 32) - 1;
                 b >= sg * (NBUCK / 32); b--) {
                cum += s_hist[b];
                if (cum >= KK) { bsel = b; break; }
            }
            s_bsel = bsel;
        }
        __syncthreads();
        const int bsel = s_bsel;
        for (int e = tid; e < NN; e += THREADS) {
            float x = ip[(size_t)e * 5 + 4];
            if ((int)(fkey(x) >> 21) >= bsel) {
                int pos = atomicAdd(&s_cnt, 1);
                if (pos < CAP) {
                    s_key[pos] = make_cand(x, e);
                    s_box[pos] = build_box(ip, anchors, e);
                }
            }
        }
        __syncthreads();
    }

    const int C = min(s_cnt, CAP);

    // ---- rank selection: exact top-K (keys unique) ----
    for (int c = tid; c < C; c += THREADS) {
        unsigned long long key = s_key[c];
        int rank = 0;
        #pragma unroll 8
        for (int j = 0; j < C; j++) rank += (s_key[j] > key) ? 1 : 0;
        if (rank < KK) {
            s_sele[rank] = c;
            s_selc[rank] = __uint_as_float((unsigned)(key >> 32) ^ 0x80000000u);
        }
    }
    __syncthreads();

    if (tid < KK) {
        float4 b = s_box[s_sele[tid]];
        s_bx1[tid] = b.x; s_by1[tid] = b.y; s_bx2[tid] = b.z; s_by2[tid] = b.w;
        s_ba[tid] = (b.z - b.x) * (b.w - b.y);
        if (s_selc[tid] >= 0.5f) atomicOr(&s_kw[tid >> 5], 1u << (tid & 31));
    }
    __syncthreads();

    // ---- pairwise pred-pred suppression bitmask (conditional atomics, rare) ----
    for (int q = tid; q < KK * KK; q += THREADS) {
        int i = q % KK, j = q / KK;
        if (j > i) {
            float lx = fmaxf(s_bx1[i], s_bx1[j]);
            float ly = fmaxf(s_by1[i], s_by1[j]);
            float rx = fminf(s_bx2[i], s_bx2[j]);
            float ry = fminf(s_by2[i], s_by2[j]);
            float iw = fmaxf(rx - lx, 0.0f), ih = fmaxf(ry - ly, 0.0f);
            float inter = iw * ih;
            float iou = __fdividef(inter, s_ba[i] + s_ba[j] - inter + EPS_);
            if (iou > 0.5f) atomicOr(&s_sup[i][j >> 5], 1u << (j & 31));
        }
    }
    __syncthreads();

    // ---- greedy NMS sweep (exact reference semantics), serial in thread 0 ----
    if (tid == 0) {
        const uint4* supv = (const uint4*)s_sup;
        unsigned kw0 = s_kw[0], kw1 = s_kw[1], kw2 = s_kw[2], kw3 = s_kw[3];
        #pragma unroll 4
        for (int i = 0; i < KK; i++) {
            uint4 r = supv[i];
            unsigned wv = (i < 32) ? kw0 : (i < 64) ? kw1 : (i < 96) ? kw2 : kw3;
            if ((wv >> (i & 31)) & 1u) {
                kw0 &= ~r.x; kw1 &= ~r.y; kw2 &= ~r.z; kw3 &= ~r.w;
            }
        }
        s_kw[0] = kw0; s_kw[1] = kw1; s_kw[2] = kw2; s_kw[3] = kw3;
    }
    __syncthreads();

    // ---- per-target max-IoU argmax: warp-owned targets, shuffle reduce ----
    {
        const int w = tid >> 5, l = tid & 31;
        unsigned kw[4] = { s_kw[0], s_kw[1], s_kw[2], s_kw[3] };
        for (int t = w; t < KK; t += THREADS / 32) {
            float tx1 = s_tx1[t], ty1 = s_ty1[t], tx2 = s_tx2[t], ty2 = s_ty2[t];
            float ta = (tx2 - tx1) * (ty2 - ty1);
            unsigned long long best = 0ull;
            #pragma unroll
            for (int p = l; p < KK + 28; p += 32) {
                if (p < KK) {
                    float kf = ((kw[p >> 5] >> (p & 31)) & 1u) ? 1.0f : 0.0f;
                    float lx = fmaxf(s_bx1[p], tx1);
                    float ly = fmaxf(s_by1[p], ty1);
                    float rx = fminf(s_bx2[p], tx2);
                    float ry = fminf(s_by2[p], ty2);
                    float iw = fmaxf(rx - lx, 0.0f), ih = fmaxf(ry - ly, 0.0f);
                    float inter = iw * ih;
                    float iou = __fdividef(inter, s_ba[p] + ta - inter + EPS_);
                    float v = iou * kf;
                    unsigned long long key =
                        ((unsigned long long)__float_as_uint(v) << 32)
                        | (unsigned)(0xFFFFFFFFu - (unsigned)p);
                    best = (key > best) ? key : best;
                }
            }
            #pragma unroll
            for (int off = 16; off; off >>= 1) {
                unsigned long long o = __shfl_down_sync(0xFFFFFFFFu, best, off);
                best = (o > best) ? o : best;
            }
            if (l == 0) s_best[t] = best;
        }
    }
    __syncthreads();

    // ---- per-target DIoU + penalty terms ----
    float diou = 0.0f, lowv = 0.0f, highv = 0.0f;
    if (tid < KK) {
        unsigned long long key = s_best[tid];
        float max_iou = fmaxf(__uint_as_float((unsigned)(key >> 32)), 0.0f);
        int best = (int)(0xFFFFFFFFu - (unsigned)(key & 0xFFFFFFFFull));
        float tx1 = s_tx1[tid], ty1 = s_ty1[tid], tx2 = s_tx2[tid], ty2 = s_ty2[tid];
        float pbx1 = s_bx1[best], pby1 = s_by1[best];
        float pbx2 = s_bx2[best], pby2 = s_by2[best];
        float pcx = (pbx1 + pbx2) * 0.5f, pcy = (pby1 + pby2) * 0.5f;
        float tcx = (tx1 + tx2) * 0.5f,  tcy = (ty1 + ty2) * 0.5f;
        float cd = (pcx - tcx) * (pcx - tcx) + (pcy - tcy) * (pcy - tcy);
        float ex1 = fminf(pbx1, tx1), ey1 = fminf(pby1, ty1);
        float ex2 = fmaxf(pbx2, tx2), ey2 = fmaxf(pby2, ty2);
        float dg = (ex2 - ex1) * (ex2 - ex1) + (ey2 - ey1) * (ey2 - ey1);
        diou = 1.0f - (max_iou - __fdividef(cd, dg + EPS_));

        float kfr = ((s_kw[tid >> 5] >> (tid & 31)) & 1u) ? 1.0f : 0.0f;
        float val = s_selc[tid];
        lowv  = fmaxf(-val, 0.0f) * kfr;
        highv = fmaxf(val - 1.0f, 0.0f) * kfr;
    }

    // deterministic reduction
    #pragma unroll
    for (int off = 16; off; off >>= 1) {
        diou  += __shfl_down_sync(0xFFFFFFFFu, diou,  off);
        lowv  += __shfl_down_sync(0xFFFFFFFFu, lowv,  off);
        highv += __shfl_down_sync(0xFFFFFFFFu, highv, off);
    }
    if ((tid & 31) == 0) {
        s_red[0][tid >> 5] = diou;
        s_red[1][tid >> 5] = lowv;
        s_red[2][tid >> 5] = highv;
    }
    __syncthreads();
    if (tid == 0) {
        float d = 0.0f, l = 0.0f, h = 0.0f;
        #pragma unroll
        for (int w = 0; w < 4; w++) {           // only warps 0-3 hold tid<KK data
            d += s_red[0][w]; l += s_red[1][w]; h += s_red[2][w];
        }
        float cnt = (float)(__popc(s_kw[0]) + __popc(s_kw[1]) +
                            __popc(s_kw[2]) + __popc(s_kw[3]));
        g_scratch[img * 4 + 0] = d;
        g_scratch[img * 4 + 1] = l;
        g_scratch[img * 4 + 2] = h;
        g_scratch[img * 4 + 3] = cnt;
        __threadfence();
        unsigned t = atomicAdd(&g_done, 1u);
        s_last = (t == BB - 1) ? 1 : 0;
    }
    __syncthreads();

    // ---- last CTA performs the global finalize ----
    if (s_last) {
        __threadfence();
        float d = 0.0f, l = 0.0f, h = 0.0f, c = 0.0f;
        if (tid < BB) {
            d = g_scratch[tid * 4 + 0];
            l = g_scratch[tid * 4 + 1];
            h = g_scratch[tid * 4 + 2];
            c = g_scratch[tid * 4 + 3];
        }
        #pragma unroll
        for (int off = 16; off; off >>= 1) {
            d += __shfl_down_sync(0xFFFFFFFFu, d, off);
            l += __shfl_down_sync(0xFFFFFFFFu, l, off);
            h += __shfl_down_sync(0xFFFFFFFFu, h, off);
            c += __shfl_down_sync(0xFFFFFFFFu, c, off);
        }
        if ((tid & 31) == 0) {
            s_red[0][tid >> 5] = d;
            s_red[1][tid >> 5] = l;
            s_red[2][tid >> 5] = h;
            s_cpart[tid >> 5]  = __float_as_uint(c);
        }
        __syncthreads();
        if (tid == 0) {
            float D = 0.0f, L = 0.0f, H = 0.0f, Cn = 0.0f;
            #pragma unroll
            for (int w = 0; w < 4; w++) {       // only warps 0-3 hold tid<BB data
                D += s_red[0][w]; L += s_red[1][w]; H += s_red[2][w];
                Cn += __uint_as_float(s_cpart[w]);
            }
            float n = fmaxf(Cn, 1.0f);
            out[0] = D / (float)(BB * KK) + L / n + 0.5f * (H / n);
            g_done = 0;                 // reset for next graph replay
        }
    }
}

extern "C" void kernel_launch(void* const* d_in, const int* in_sizes, int n_in,
                              void* d_out, int out_size)
{
    const float* output  = (const float*)d_in[0];   // (128,64,64,9,5) fp32
    const float* tboxes  = (const float*)d_in[1];   // (128,100,4) fp32
    const float* anchors = (const float*)d_in[2];   // (9,2) fp32
    float* out = (float*)d_out;

    fused_kernel<<<BB, THREADS>>>(output, tboxes, anchors, out);
}